// round 12
// baseline (speedup 1.0000x reference)
#include <cuda_runtime.h>
#include <cuda_fp16.h>
#include <math.h>
#include <stdint.h>

// Problem constants (fixed shapes for this problem)
#define HN 100000      // nodes per type
#define EN 200000      // edges per edge type
#define HDIM 128       // hidden
#define NHEAD 4
#define DHEAD 32

static const float INV_SQRT_D = 0.17677669529663687f; // 1/sqrt(32)

// ---------------- scratch layout ----------------
constexpr size_t SN = (size_t)HN * HDIM;       // one [N,128] fp32 buffer (= N*512 bytes)
constexpr size_t O_XS0   = 0;
constexpr size_t O_XS1   = SN;
constexpr size_t O_Q0    = 2*SN;               // fp16 [N,128] (half used)
constexpr size_t O_Q1    = 3*SN;
constexpr size_t O_KTVT0 = 4*SN;               // fp16 [N,256] = exactly SN floats
constexpr size_t O_KTVT1 = 5*SN;
constexpr size_t O_KTVT2 = 6*SN;
constexpr size_t O_AG0   = 7*SN;               // fp32 [N,128] pre-activated finalize input
constexpr size_t O_AG1   = 8*SN;
constexpr size_t O_PW    = 9*SN;               // 16 chunks of 128*128
constexpr size_t O_PB    = O_PW + (size_t)16*HDIM*HDIM;
constexpr size_t O_CSR   = O_PB + (size_t)16*HDIM;   // int region (1 int = 1 float slot)
// int offsets within CSR region:
//   deg0:[0,N) deg1:[N,2N) off0:[2N,3N+1) off1:[3N+1,4N+2)
//   cur0:[4N+2,5N+2) cur1:[5N+2,6N+2) list0:[6N+2,6N+2+EN) list1:[...,+2EN)
constexpr size_t CSR_INTS = (size_t)6*HN + 2 + (size_t)3*EN;
constexpr size_t SCRATCH_TOTAL = O_CSR + CSR_INTS;

__device__ float g_scratch[SCRATCH_TOTAL];

// ---------------- helpers ----------------
__device__ __forceinline__ float gelu_exact(float x) {
    return 0.5f * x * (1.0f + erff(x * 0.70710678118654752f));
}

__device__ __forceinline__ uint32_t f2tf32(float x) {
    uint32_t u;
    asm("cvt.rna.tf32.f32 %0, %1;" : "=r"(u) : "f"(x));
    return u;
}

__device__ __forceinline__ void mma_tf32(float c[4], const uint32_t a[4], const uint32_t b[2]) {
    asm volatile(
        "mma.sync.aligned.m16n8k8.row.col.f32.tf32.tf32.f32 "
        "{%0,%1,%2,%3}, {%4,%5,%6,%7}, {%8,%9}, {%0,%1,%2,%3};"
        : "+f"(c[0]), "+f"(c[1]), "+f"(c[2]), "+f"(c[3])
        : "r"(a[0]), "r"(a[1]), "r"(a[2]), "r"(a[3]), "r"(b[0]), "r"(b[1]));
}

// ---------------- pack kernel (unchanged chunk map) ----------------
__global__ void pack_kernel(const float* __restrict__ Wq, const float* __restrict__ bq,
                            const float* __restrict__ Wk, const float* __restrict__ bk,
                            const float* __restrict__ Wv, const float* __restrict__ bv,
                            const float* __restrict__ Krel, const float* __restrict__ Vrel,
                            float* __restrict__ PW, float* __restrict__ PB)
{
    int b = blockIdx.x;     // 0..15
    int l = b >> 3, c = b & 7;
    float* WO = PW + (size_t)b * HDIM * HDIM;
    float* bO = PB + (size_t)b * HDIM;

    if (c == 0 || c == 3) {
        int t = (c == 3);
        const float* W = Wq + (size_t)(l*2 + t) * HDIM * HDIM;
        const float* bb = bq + (size_t)(l*2 + t) * HDIM;
        for (int i = threadIdx.x; i < HDIM*HDIM; i += blockDim.x) WO[i] = W[i];
        if (threadIdx.x < HDIM) bO[threadIdx.x] = bb[threadIdx.x];
        return;
    }

    int kv, r, s;
    if (c == 1) { kv = 0; r = 0; s = 0; }
    else if (c == 2) { kv = 1; r = 0; s = 0; }
    else if (c == 4) { kv = 0; r = 1; s = 1; }
    else if (c == 5) { kv = 1; r = 1; s = 1; }
    else if (c == 6) { kv = 0; r = 2; s = 1; }
    else { kv = 1; r = 2; s = 1; }

    const float* W  = (kv ? Wv : Wk) + (size_t)(l*2 + s) * HDIM * HDIM;
    const float* bb = (kv ? bv : bk) + (size_t)(l*2 + s) * HDIM;
    const float* R  = (kv ? Vrel : Krel) + (size_t)(l*3 + r) * NHEAD * DHEAD * DHEAD;

    __shared__ float Rs[NHEAD*DHEAD*DHEAD];
    for (int i = threadIdx.x; i < NHEAD*DHEAD*DHEAD; i += blockDim.x) Rs[i] = R[i];
    __syncthreads();

    for (int o = threadIdx.x; o < HDIM*HDIM; o += blockDim.x) {
        int i = o >> 7, j = o & 127;
        int h = j >> 5, e = j & 31;
        float sum = 0.f;
        #pragma unroll
        for (int d = 0; d < DHEAD; d++)
            sum += W[i*HDIM + h*DHEAD + d] * Rs[(h*DHEAD + d)*DHEAD + e];
        WO[o] = sum;
    }
    if (threadIdx.x < HDIM) {
        int j = threadIdx.x, h = j >> 5, e = j & 31;
        float sum = 0.f;
        #pragma unroll
        for (int d = 0; d < DHEAD; d++)
            sum += bb[h*DHEAD + d] * Rs[(h*DHEAD + d)*DHEAD + e];
        bO[j] = sum;
    }
}

// ---------------- single-output tf32 GEMM, fp32 out (input proj + finalize) ----------------
// flags bit1: post skip-blend + relu (reads Cold)
template<int K>
__global__ __launch_bounds__(256) void mma_gemm(
        const float* __restrict__ A, const float* __restrict__ B,
        const float* __restrict__ bias, float* __restrict__ C,
        const float* __restrict__ Cold, const float* __restrict__ skipPtr,
        int N, int flags)
{
    constexpr int KP = K + 4;
    constexpr int K4 = K / 4;
    extern __shared__ uint32_t smu[];
    uint32_t* As = smu;                  // 128 * KP
    uint32_t* Bs = smu + 128*KP;         // K * 132
    float* biass = (float*)(Bs + K*132); // 128

    int tid = threadIdx.x;
    int row0 = blockIdx.x * 128;

    if (tid < 128) biass[tid] = bias[tid];

    const float4* B4 = (const float4*)B;
    for (int i = tid; i < K*32; i += 256) {
        int k = i >> 5, c4 = i & 31;
        float4 v = B4[i];
        uint32_t* dst = &Bs[k*132 + c4*4];
        dst[0] = f2tf32(v.x); dst[1] = f2tf32(v.y);
        dst[2] = f2tf32(v.z); dst[3] = f2tf32(v.w);
    }

    for (int i = tid; i < 128*K4; i += 256) {
        int r = i / K4, c4 = i % K4;
        int n = row0 + r;
        float4 v = make_float4(0.f, 0.f, 0.f, 0.f);
        if (n < N) v = ((const float4*)A)[(size_t)n*K4 + c4];
        uint32_t* dst = &As[r*KP + c4*4];
        dst[0] = f2tf32(v.x); dst[1] = f2tf32(v.y);
        dst[2] = f2tf32(v.z); dst[3] = f2tf32(v.w);
    }
    __syncthreads();

    int lane = tid & 31, w = tid >> 5;
    int wm = (w & 1) * 64;
    int wn = (w >> 1) * 32;
    int lg = lane >> 2;
    int lt = lane & 3;

    float acc[4][4][4];
    #pragma unroll
    for (int mt = 0; mt < 4; mt++)
        #pragma unroll
        for (int nt = 0; nt < 4; nt++)
            #pragma unroll
            for (int j = 0; j < 4; j++) acc[mt][nt][j] = 0.f;

    #pragma unroll 2
    for (int k0 = 0; k0 < K; k0 += 8) {
        uint32_t af[4][4];
        #pragma unroll
        for (int mt = 0; mt < 4; mt++) {
            int r = wm + mt*16 + lg;
            af[mt][0] = As[r*KP + k0 + lt];
            af[mt][1] = As[(r+8)*KP + k0 + lt];
            af[mt][2] = As[r*KP + k0 + lt + 4];
            af[mt][3] = As[(r+8)*KP + k0 + lt + 4];
        }
        uint32_t bf[4][2];
        #pragma unroll
        for (int nt = 0; nt < 4; nt++) {
            bf[nt][0] = Bs[(k0 + lt)*132 + wn + nt*8 + lg];
            bf[nt][1] = Bs[(k0 + lt + 4)*132 + wn + nt*8 + lg];
        }
        #pragma unroll
        for (int mt = 0; mt < 4; mt++)
            #pragma unroll
            for (int nt = 0; nt < 4; nt++)
                mma_tf32(acc[mt][nt], af[mt], bf[nt]);
    }

    bool blend = flags & 2;
    float askip = 0.f;
    if (blend) askip = 1.f / (1.f + expf(-skipPtr[0]));

    #pragma unroll
    for (int mt = 0; mt < 4; mt++) {
        #pragma unroll
        for (int nt = 0; nt < 4; nt++) {
            int col = wn + nt*8 + lt*2;
            float b0 = biass[col], b1 = biass[col+1];
            #pragma unroll
            for (int half = 0; half < 2; half++) {
                int r = row0 + wm + mt*16 + lg + half*8;
                if (r >= N) continue;
                float2 o;
                o.x = acc[mt][nt][half*2 + 0] + b0;
                o.y = acc[mt][nt][half*2 + 1] + b1;
                if (blend) {
                    float2 old = *(const float2*)&Cold[(size_t)r*HDIM + col];
                    o.x = fmaxf(askip*o.x + (1.f-askip)*old.x, 0.f);
                    o.y = fmaxf(askip*o.y + (1.f-askip)*old.y, 0.f);
                }
                *(float2*)&C[(size_t)r*HDIM + col] = o;
            }
        }
    }
}

// ---------------- multi-output tf32 GEMM: A staged once, NC chunks, FP16 outputs ----------------
struct MultiOut {
    __half* ptr[5];
    int     stride[5];   // in half elements
};

template<int NC>
__global__ __launch_bounds__(256) void mma_gemm_multi(
        const float* __restrict__ A, const float* __restrict__ PW,
        const float* __restrict__ PB, MultiOut mo, int N)
{
    constexpr int KP = HDIM + 4;
    extern __shared__ uint32_t smu[];
    uint32_t* As = smu;            // 128 * KP
    uint32_t* Bs = smu + 128*KP;   // 128 * 132

    int tid = threadIdx.x;
    int row0 = blockIdx.x * 128;

    for (int i = tid; i < 128*32; i += 256) {
        int r = i >> 5, c4 = i & 31;
        int n = row0 + r;
        float4 v = make_float4(0.f, 0.f, 0.f, 0.f);
        if (n < N) v = ((const float4*)A)[(size_t)n*32 + c4];
        uint32_t* dst = &As[r*KP + c4*4];
        dst[0] = f2tf32(v.x); dst[1] = f2tf32(v.y);
        dst[2] = f2tf32(v.z); dst[3] = f2tf32(v.w);
    }

    int lane = tid & 31, w = tid >> 5;
    int wm = (w & 1) * 64;
    int wn = (w >> 1) * 32;
    int lg = lane >> 2;
    int lt = lane & 3;

    #pragma unroll
    for (int c = 0; c < NC; c++) {
        __syncthreads();
        const float4* B4 = (const float4*)(PW + (size_t)c * HDIM * HDIM);
        for (int i = tid; i < 128*32; i += 256) {
            int k = i >> 5, c4 = i & 31;
            float4 v = B4[i];
            uint32_t* dst = &Bs[k*132 + c4*4];
            dst[0] = f2tf32(v.x); dst[1] = f2tf32(v.y);
            dst[2] = f2tf32(v.z); dst[3] = f2tf32(v.w);
        }
        __syncthreads();

        float acc[4][4][4];
        #pragma unroll
        for (int mt = 0; mt < 4; mt++)
            #pragma unroll
            for (int nt = 0; nt < 4; nt++)
                #pragma unroll
                for (int j = 0; j < 4; j++) acc[mt][nt][j] = 0.f;

        #pragma unroll 2
        for (int k0 = 0; k0 < HDIM; k0 += 8) {
            uint32_t af[4][4];
            #pragma unroll
            for (int mt = 0; mt < 4; mt++) {
                int r = wm + mt*16 + lg;
                af[mt][0] = As[r*KP + k0 + lt];
                af[mt][1] = As[(r+8)*KP + k0 + lt];
                af[mt][2] = As[r*KP + k0 + lt + 4];
                af[mt][3] = As[(r+8)*KP + k0 + lt + 4];
            }
            uint32_t bf[4][2];
            #pragma unroll
            for (int nt = 0; nt < 4; nt++) {
                bf[nt][0] = Bs[(k0 + lt)*132 + wn + nt*8 + lg];
                bf[nt][1] = Bs[(k0 + lt + 4)*132 + wn + nt*8 + lg];
            }
            #pragma unroll
            for (int mt = 0; mt < 4; mt++)
                #pragma unroll
                for (int nt = 0; nt < 4; nt++)
                    mma_tf32(acc[mt][nt], af[mt], bf[nt]);
        }

        __half* out = mo.ptr[c];
        int st = mo.stride[c];
        const float* bb = PB + (size_t)c * HDIM;
        #pragma unroll
        for (int mt = 0; mt < 4; mt++) {
            #pragma unroll
            for (int nt = 0; nt < 4; nt++) {
                int col = wn + nt*8 + lt*2;
                float b0 = bb[col], b1 = bb[col+1];
                #pragma unroll
                for (int half = 0; half < 2; half++) {
                    int r = row0 + wm + mt*16 + lg + half*8;
                    if (r >= N) continue;
                    __half2 hv = __floats2half2_rn(acc[mt][nt][half*2 + 0] + b0,
                                                   acc[mt][nt][half*2 + 1] + b1);
                    *(__half2*)&out[(size_t)r*st + col] = hv;
                }
            }
        }
    }
}

// ---------------- CSR build ----------------
__global__ void csr_zero(int* __restrict__ deg0, int* __restrict__ deg1, int N) {
    int i = blockIdx.x * blockDim.x + threadIdx.x;
    if (i < N) { deg0[i] = 0; deg1[i] = 0; }
}

__global__ void csr_hist(const int* __restrict__ e0, const int* __restrict__ e1,
                         const int* __restrict__ e2, int E,
                         int* __restrict__ deg0, int* __restrict__ deg1) {
    int i = blockIdx.x * blockDim.x + threadIdx.x;
    if (i >= 3*E) return;
    int r = i / E, j = i - r*E;
    const int* e = (r == 0) ? e0 : (r == 1 ? e1 : e2);
    int dst = e[E + j];
    if (r == 1) atomicAdd(&deg0[dst], 1);
    else        atomicAdd(&deg1[dst], 1);
}

// single-block exclusive scan of deg0 and deg1 (1024 threads)
__global__ void csr_scan(const int* __restrict__ deg0, const int* __restrict__ deg1,
                         int* __restrict__ off0, int* __restrict__ off1,
                         int* __restrict__ cur0, int* __restrict__ cur1, int N) {
    __shared__ int wsum[32];
    __shared__ int carrysh;
    int lane = threadIdx.x & 31, wid = threadIdx.x >> 5;
    for (int a = 0; a < 2; a++) {
        const int* deg = a ? deg1 : deg0;
        int* off = a ? off1 : off0;
        int* cur = a ? cur1 : cur0;
        if (threadIdx.x == 0) carrysh = 0;
        __syncthreads();
        for (int base = 0; base < N; base += 1024) {
            int i = base + threadIdx.x;
            int v = (i < N) ? deg[i] : 0;
            int incl = v;
            #pragma unroll
            for (int s = 1; s < 32; s <<= 1) {
                int t = __shfl_up_sync(0xffffffffu, incl, s);
                if (lane >= s) incl += t;
            }
            if (lane == 31) wsum[wid] = incl;
            __syncthreads();
            if (wid == 0) {
                int ws = wsum[lane];
                int wincl = ws;
                #pragma unroll
                for (int s = 1; s < 32; s <<= 1) {
                    int t = __shfl_up_sync(0xffffffffu, wincl, s);
                    if (lane >= s) wincl += t;
                }
                wsum[lane] = wincl - ws;   // exclusive warp offsets
            }
            __syncthreads();
            int excl = carrysh + wsum[wid] + incl - v;
            if (i < N) { off[i] = excl; cur[i] = excl; }
            __syncthreads();
            if (threadIdx.x == 1023) carrysh += wsum[31] + incl;
            __syncthreads();
        }
        if (threadIdx.x == 0) off[N] = carrysh;
        __syncthreads();
    }
}

__global__ void csr_fill(const int* __restrict__ e0, const int* __restrict__ e1,
                         const int* __restrict__ e2, int E,
                         int* __restrict__ cur0, int* __restrict__ cur1,
                         int* __restrict__ list0, int* __restrict__ list1) {
    int i = blockIdx.x * blockDim.x + threadIdx.x;
    if (i >= 3*E) return;
    int r = i / E, j = i - r*E;
    const int* e = (r == 0) ? e0 : (r == 1 ? e1 : e2);
    int src = e[j], dst = e[E + j];
    if (r == 1) {
        int p = atomicAdd(&cur0[dst], 1);
        list0[p] = src;
    } else {
        int p = atomicAdd(&cur1[dst], 1);
        list1[p] = src | ((r == 2) ? (1 << 20) : 0);
    }
}

// ---------------- gather edge pass: warp per dst node, register accumulation ----------------
// Writes Ag[n] = gelu(msg[n]/den[n]) directly (0 if no in-edges).
template<bool TWO>
__global__ void gather_kernel(const int* __restrict__ off, const int* __restrict__ list,
                              const __half* __restrict__ q,
                              const __half* __restrict__ kva, const __half* __restrict__ kvb,
                              const float* __restrict__ prelA, const float* __restrict__ prelB,
                              float* __restrict__ Ag, int N)
{
    int g = blockIdx.x * blockDim.x + threadIdx.x;
    int w = g >> 5;
    if (w >= N) return;
    int lane = threadIdx.x & 31;
    int h = lane >> 3, sub = lane & 7;
    int col = h*DHEAD + sub*4;

    const __half2* qp = (const __half2*)&q[(size_t)w*HDIM + col];
    float2 q0 = __half22float2(qp[0]), q1 = __half22float2(qp[1]);
    float pA = __ldg(&prelA[h]) * INV_SQRT_D;
    float pB = TWO ? (__ldg(&prelB[h]) * INV_SQRT_D) : 0.f;

    float den = 0.f;
    float4 macc = make_float4(0.f, 0.f, 0.f, 0.f);
    int s0 = __ldg(&off[w]), s1 = __ldg(&off[w+1]);
    for (int j = s0; j < s1; j++) {
        int entry = __ldg(&list[j]);
        int src = entry & 0xFFFFF;
        const __half* kvbase = kva;
        float p = pA;
        if (TWO && (entry >> 20)) { kvbase = kvb; p = pB; }
        const __half2* kp = (const __half2*)&kvbase[(size_t)src*256 + col];
        const __half2* vp = (const __half2*)&kvbase[(size_t)src*256 + 128 + col];
        float2 k0 = __half22float2(kp[0]), k1 = __half22float2(kp[1]);
        float2 v0 = __half22float2(vp[0]), v1 = __half22float2(vp[1]);
        float s = q0.x*k0.x + q0.y*k0.y + q1.x*k1.x + q1.y*k1.y;
        s += __shfl_xor_sync(0xffffffffu, s, 1);
        s += __shfl_xor_sync(0xffffffffu, s, 2);
        s += __shfl_xor_sync(0xffffffffu, s, 4);
        float e = expf(s * p);
        den += e;
        macc.x += e*v0.x; macc.y += e*v0.y; macc.z += e*v1.x; macc.w += e*v1.y;
    }
    float inv = (den > 0.f) ? 1.f/den : 0.f;
    float4 o;
    o.x = gelu_exact(macc.x * inv);
    o.y = gelu_exact(macc.y * inv);
    o.z = gelu_exact(macc.z * inv);
    o.w = gelu_exact(macc.w * inv);
    *(float4*)&Ag[(size_t)w*HDIM + col] = o;
}

// ---------------- host orchestration ----------------
extern "C" void kernel_launch(void* const* d_in, const int* in_sizes, int n_in,
                              void* d_out, int out_size)
{
    const float* x_region = (const float*)d_in[0];
    const float* x_site   = (const float*)d_in[1];
    const float* pWr = (const float*)d_in[2];
    const float* pbr = (const float*)d_in[3];
    const float* pWs = (const float*)d_in[4];
    const float* pbs = (const float*)d_in[5];
    const float* Wk  = (const float*)d_in[6];
    const float* bk  = (const float*)d_in[7];
    const float* Wq  = (const float*)d_in[8];
    const float* bq  = (const float*)d_in[9];
    const float* Wv  = (const float*)d_in[10];
    const float* bv  = (const float*)d_in[11];
    const float* Wo  = (const float*)d_in[12];
    const float* bo  = (const float*)d_in[13];
    const float* skip = (const float*)d_in[14];
    const float* Krel = (const float*)d_in[15];
    const float* Vrel = (const float*)d_in[16];
    const float* prel = (const float*)d_in[17];
    const int* edges[3] = { (const int*)d_in[18], (const int*)d_in[19], (const int*)d_in[20] };

    int N = in_sizes[0] / 64;
    int E = in_sizes[18] / 2;

    float* base = nullptr;
    cudaGetSymbolAddress((void**)&base, g_scratch);

    float* xs[2]    = { base + O_XS0,  base + O_XS1 };
    __half* qb[2]   = { (__half*)(base + O_Q0), (__half*)(base + O_Q1) };
    __half* ktvt[3] = { (__half*)(base + O_KTVT0), (__half*)(base + O_KTVT1), (__half*)(base + O_KTVT2) };
    float* Ag[2]    = { base + O_AG0, base + O_AG1 };
    float* PW = base + O_PW;
    float* PB = base + O_PB;
    int* ci = (int*)(base + O_CSR);
    int* deg0 = ci;           int* deg1 = ci + HN;
    int* off0 = ci + 2*HN;    int* off1 = ci + 3*HN + 1;
    int* cur0 = ci + 4*HN + 2; int* cur1 = ci + 5*HN + 2;
    int* list0 = ci + 6*HN + 2; int* list1 = list0 + EN;

    const int SM128 = (128*132 + 128*132 + 128) * 4;
    const int SM64  = (128*68  + 64*132  + 128) * 4;
    const int SM32  = (128*36  + 32*132  + 128) * 4;
    const int SMM   = (128*132 + 128*132) * 4;
    cudaFuncSetAttribute(mma_gemm<128>, cudaFuncAttributeMaxDynamicSharedMemorySize, SM128);
    cudaFuncSetAttribute(mma_gemm<64>,  cudaFuncAttributeMaxDynamicSharedMemorySize, SM64);
    cudaFuncSetAttribute(mma_gemm<32>,  cudaFuncAttributeMaxDynamicSharedMemorySize, SM32);
    cudaFuncSetAttribute(mma_gemm_multi<3>, cudaFuncAttributeMaxDynamicSharedMemorySize, SMM);
    cudaFuncSetAttribute(mma_gemm_multi<5>, cudaFuncAttributeMaxDynamicSharedMemorySize, SMM);

    int gemmGrid = (N + 127) / 128;
    int nodeGrid = (N*32 + 255) / 256;
    int eGrid3   = (3*E + 255) / 256;
    int nGrid    = (N + 255) / 256;

    // 0) packed weight chunks + CSR build (edges constant across layers)
    pack_kernel<<<16, 256>>>(Wq, bq, Wk, bk, Wv, bv, Krel, Vrel, PW, PB);
    csr_zero<<<nGrid, 256>>>(deg0, deg1, N);
    csr_hist<<<eGrid3, 256>>>(edges[0], edges[1], edges[2], E, deg0, deg1);
    csr_scan<<<1, 1024>>>(deg0, deg1, off0, off1, cur0, cur1, N);
    csr_fill<<<eGrid3, 256>>>(edges[0], edges[1], edges[2], E, cur0, cur1, list0, list1);

    // 1) input projections
    mma_gemm<64><<<gemmGrid, 256, SM64>>>(x_region, pWr, pbr, xs[0], nullptr, nullptr, N, 0);
    mma_gemm<32><<<gemmGrid, 256, SM32>>>(x_site,   pWs, pbs, xs[1], nullptr, nullptr, N, 0);

    const int L = 2;
    for (int l = 0; l < L; l++) {
        // type 0: q + ktvt for edge type 0  (chunks 0..2)
        {
            MultiOut mo;
            mo.ptr[0] = qb[0];          mo.stride[0] = 128;
            mo.ptr[1] = ktvt[0];        mo.stride[1] = 256;
            mo.ptr[2] = ktvt[0] + 128;  mo.stride[2] = 256;
            mo.ptr[3] = nullptr; mo.ptr[4] = nullptr;
            mo.stride[3] = 0; mo.stride[4] = 0;
            mma_gemm_multi<3><<<gemmGrid, 256, SMM>>>(xs[0], PW + (size_t)(l*8+0)*HDIM*HDIM,
                                                      PB + (size_t)(l*8+0)*HDIM, mo, N);
        }
        // type 1: q + ktvt for edge types 1,2  (chunks 3..7)
        {
            MultiOut mo;
            mo.ptr[0] = qb[1];          mo.stride[0] = 128;
            mo.ptr[1] = ktvt[1];        mo.stride[1] = 256;
            mo.ptr[2] = ktvt[1] + 128;  mo.stride[2] = 256;
            mo.ptr[3] = ktvt[2];        mo.stride[3] = 256;
            mo.ptr[4] = ktvt[2] + 128;  mo.stride[4] = 256;
            mma_gemm_multi<5><<<gemmGrid, 256, SMM>>>(xs[1], PW + (size_t)(l*8+3)*HDIM*HDIM,
                                                      PB + (size_t)(l*8+3)*HDIM, mo, N);
        }

        // gather edge pass (per dst type), writes pre-activated finalize input
        // type 0 dst: edge type r1 (src type 1, ktvt[1], prel[l][1])
        gather_kernel<false><<<nodeGrid, 256>>>(off0, list0, qb[0], ktvt[1], nullptr,
                                                prel + (size_t)(l*3+1)*NHEAD, nullptr,
                                                Ag[0], N);
        // type 1 dst: edge types r0 (ktvt[0], prel[l][0]) and r2 (ktvt[2], prel[l][2])
        gather_kernel<true><<<nodeGrid, 256>>>(off1, list1, qb[1], ktvt[0], ktvt[2],
                                               prel + (size_t)(l*3+0)*NHEAD,
                                               prel + (size_t)(l*3+2)*NHEAD,
                                               Ag[1], N);

        // finalize: out = relu(a*(Ag@Wo + bo) + (1-a)*xs)
        for (int t = 0; t < 2; t++) {
            float* Cptr = (l == L-1) ? ((float*)d_out + (size_t)t*N*HDIM) : xs[t];
            mma_gemm<128><<<gemmGrid, 256, SM128>>>(Ag[t], Wo + (size_t)(l*2+t)*HDIM*HDIM,
                                                    bo + (size_t)(l*2+t)*HDIM, Cptr,
                                                    xs[t], skip + l*2 + t, N, 2);
        }
    }
}

// round 13
// speedup vs baseline: 1.0763x; 1.0763x over previous
#include <cuda_runtime.h>
#include <cuda_fp16.h>
#include <math.h>
#include <stdint.h>

// Problem constants (fixed shapes for this problem)
#define HN 100000      // nodes per type
#define EN 200000      // edges per edge type
#define HDIM 128       // hidden
#define NHEAD 4
#define DHEAD 32

static const float INV_SQRT_D = 0.17677669529663687f; // 1/sqrt(32)

// ---------------- scratch layout ----------------
constexpr size_t SN = (size_t)HN * HDIM;       // one [N,128] fp32 buffer (= N*512 bytes)
constexpr size_t O_XS0   = 0;
constexpr size_t O_XS1   = SN;
constexpr size_t O_Q0    = 2*SN;               // fp16 [N,128] (half used)
constexpr size_t O_Q1    = 3*SN;
constexpr size_t O_KTVT0 = 4*SN;               // fp16 [N,256] = exactly SN floats
constexpr size_t O_KTVT1 = 5*SN;
constexpr size_t O_KTVT2 = 6*SN;
constexpr size_t O_AG0   = 7*SN;               // fp32 [N,128] pre-activated finalize input
constexpr size_t O_AG1   = 8*SN;
constexpr size_t O_PW    = 9*SN;               // 16 chunks of 128*128
constexpr size_t O_PB    = O_PW + (size_t)16*HDIM*HDIM;
constexpr size_t O_CSR   = O_PB + (size_t)16*HDIM;   // int region (1 int = 1 float slot)
// int offsets within CSR region:
//   deg0:[0,N) deg1:[N,2N) off0:[2N,3N+1) off1:[3N+1,4N+2)
//   cur0:[4N+2,5N+2) cur1:[5N+2,6N+2) bsum:[6N+2,6N+2+512)
//   list0:[6N+514, +EN) list1:[..., +2EN)
constexpr size_t CSR_INTS = (size_t)6*HN + 2 + 512 + (size_t)3*EN;
constexpr size_t SCRATCH_TOTAL = O_CSR + CSR_INTS;

__device__ float g_scratch[SCRATCH_TOTAL];

// ---------------- helpers ----------------
__device__ __forceinline__ float gelu_exact(float x) {
    return 0.5f * x * (1.0f + erff(x * 0.70710678118654752f));
}

__device__ __forceinline__ uint32_t f2tf32(float x) {
    uint32_t u;
    asm("cvt.rna.tf32.f32 %0, %1;" : "=r"(u) : "f"(x));
    return u;
}

__device__ __forceinline__ void mma_tf32(float c[4], const uint32_t a[4], const uint32_t b[2]) {
    asm volatile(
        "mma.sync.aligned.m16n8k8.row.col.f32.tf32.tf32.f32 "
        "{%0,%1,%2,%3}, {%4,%5,%6,%7}, {%8,%9}, {%0,%1,%2,%3};"
        : "+f"(c[0]), "+f"(c[1]), "+f"(c[2]), "+f"(c[3])
        : "r"(a[0]), "r"(a[1]), "r"(a[2]), "r"(a[3]), "r"(b[0]), "r"(b[1]));
}

// ---------------- pack kernel (unchanged chunk map) ----------------
__global__ void pack_kernel(const float* __restrict__ Wq, const float* __restrict__ bq,
                            const float* __restrict__ Wk, const float* __restrict__ bk,
                            const float* __restrict__ Wv, const float* __restrict__ bv,
                            const float* __restrict__ Krel, const float* __restrict__ Vrel,
                            float* __restrict__ PW, float* __restrict__ PB)
{
    int b = blockIdx.x;     // 0..15
    int l = b >> 3, c = b & 7;
    float* WO = PW + (size_t)b * HDIM * HDIM;
    float* bO = PB + (size_t)b * HDIM;

    if (c == 0 || c == 3) {
        int t = (c == 3);
        const float* W = Wq + (size_t)(l*2 + t) * HDIM * HDIM;
        const float* bb = bq + (size_t)(l*2 + t) * HDIM;
        for (int i = threadIdx.x; i < HDIM*HDIM; i += blockDim.x) WO[i] = W[i];
        if (threadIdx.x < HDIM) bO[threadIdx.x] = bb[threadIdx.x];
        return;
    }

    int kv, r, s;
    if (c == 1) { kv = 0; r = 0; s = 0; }
    else if (c == 2) { kv = 1; r = 0; s = 0; }
    else if (c == 4) { kv = 0; r = 1; s = 1; }
    else if (c == 5) { kv = 1; r = 1; s = 1; }
    else if (c == 6) { kv = 0; r = 2; s = 1; }
    else { kv = 1; r = 2; s = 1; }

    const float* W  = (kv ? Wv : Wk) + (size_t)(l*2 + s) * HDIM * HDIM;
    const float* bb = (kv ? bv : bk) + (size_t)(l*2 + s) * HDIM;
    const float* R  = (kv ? Vrel : Krel) + (size_t)(l*3 + r) * NHEAD * DHEAD * DHEAD;

    __shared__ float Rs[NHEAD*DHEAD*DHEAD];
    for (int i = threadIdx.x; i < NHEAD*DHEAD*DHEAD; i += blockDim.x) Rs[i] = R[i];
    __syncthreads();

    for (int o = threadIdx.x; o < HDIM*HDIM; o += blockDim.x) {
        int i = o >> 7, j = o & 127;
        int h = j >> 5, e = j & 31;
        float sum = 0.f;
        #pragma unroll
        for (int d = 0; d < DHEAD; d++)
            sum += W[i*HDIM + h*DHEAD + d] * Rs[(h*DHEAD + d)*DHEAD + e];
        WO[o] = sum;
    }
    if (threadIdx.x < HDIM) {
        int j = threadIdx.x, h = j >> 5, e = j & 31;
        float sum = 0.f;
        #pragma unroll
        for (int d = 0; d < DHEAD; d++)
            sum += bb[h*DHEAD + d] * Rs[(h*DHEAD + d)*DHEAD + e];
        bO[j] = sum;
    }
}

// ---------------- single-output tf32 GEMM, fp32 out (input proj + finalize) ----------------
// flags bit1: post skip-blend + relu (reads Cold)
template<int K>
__global__ __launch_bounds__(256) void mma_gemm(
        const float* __restrict__ A, const float* __restrict__ B,
        const float* __restrict__ bias, float* __restrict__ C,
        const float* __restrict__ Cold, const float* __restrict__ skipPtr,
        int N, int flags)
{
    constexpr int KP = K + 4;
    constexpr int K4 = K / 4;
    extern __shared__ uint32_t smu[];
    uint32_t* As = smu;                  // 128 * KP
    uint32_t* Bs = smu + 128*KP;         // K * 132
    float* biass = (float*)(Bs + K*132); // 128

    int tid = threadIdx.x;
    int row0 = blockIdx.x * 128;

    if (tid < 128) biass[tid] = bias[tid];

    const float4* B4 = (const float4*)B;
    for (int i = tid; i < K*32; i += 256) {
        int k = i >> 5, c4 = i & 31;
        float4 v = B4[i];
        uint32_t* dst = &Bs[k*132 + c4*4];
        dst[0] = f2tf32(v.x); dst[1] = f2tf32(v.y);
        dst[2] = f2tf32(v.z); dst[3] = f2tf32(v.w);
    }

    for (int i = tid; i < 128*K4; i += 256) {
        int r = i / K4, c4 = i % K4;
        int n = row0 + r;
        float4 v = make_float4(0.f, 0.f, 0.f, 0.f);
        if (n < N) v = ((const float4*)A)[(size_t)n*K4 + c4];
        uint32_t* dst = &As[r*KP + c4*4];
        dst[0] = f2tf32(v.x); dst[1] = f2tf32(v.y);
        dst[2] = f2tf32(v.z); dst[3] = f2tf32(v.w);
    }
    __syncthreads();

    int lane = tid & 31, w = tid >> 5;
    int wm = (w & 1) * 64;
    int wn = (w >> 1) * 32;
    int lg = lane >> 2;
    int lt = lane & 3;

    float acc[4][4][4];
    #pragma unroll
    for (int mt = 0; mt < 4; mt++)
        #pragma unroll
        for (int nt = 0; nt < 4; nt++)
            #pragma unroll
            for (int j = 0; j < 4; j++) acc[mt][nt][j] = 0.f;

    #pragma unroll 2
    for (int k0 = 0; k0 < K; k0 += 8) {
        uint32_t af[4][4];
        #pragma unroll
        for (int mt = 0; mt < 4; mt++) {
            int r = wm + mt*16 + lg;
            af[mt][0] = As[r*KP + k0 + lt];
            af[mt][1] = As[(r+8)*KP + k0 + lt];
            af[mt][2] = As[r*KP + k0 + lt + 4];
            af[mt][3] = As[(r+8)*KP + k0 + lt + 4];
        }
        uint32_t bf[4][2];
        #pragma unroll
        for (int nt = 0; nt < 4; nt++) {
            bf[nt][0] = Bs[(k0 + lt)*132 + wn + nt*8 + lg];
            bf[nt][1] = Bs[(k0 + lt + 4)*132 + wn + nt*8 + lg];
        }
        #pragma unroll
        for (int mt = 0; mt < 4; mt++)
            #pragma unroll
            for (int nt = 0; nt < 4; nt++)
                mma_tf32(acc[mt][nt], af[mt], bf[nt]);
    }

    bool blend = flags & 2;
    float askip = 0.f;
    if (blend) askip = 1.f / (1.f + expf(-skipPtr[0]));

    #pragma unroll
    for (int mt = 0; mt < 4; mt++) {
        #pragma unroll
        for (int nt = 0; nt < 4; nt++) {
            int col = wn + nt*8 + lt*2;
            float b0 = biass[col], b1 = biass[col+1];
            #pragma unroll
            for (int half = 0; half < 2; half++) {
                int r = row0 + wm + mt*16 + lg + half*8;
                if (r >= N) continue;
                float2 o;
                o.x = acc[mt][nt][half*2 + 0] + b0;
                o.y = acc[mt][nt][half*2 + 1] + b1;
                if (blend) {
                    float2 old = *(const float2*)&Cold[(size_t)r*HDIM + col];
                    o.x = fmaxf(askip*o.x + (1.f-askip)*old.x, 0.f);
                    o.y = fmaxf(askip*o.y + (1.f-askip)*old.y, 0.f);
                }
                *(float2*)&C[(size_t)r*HDIM + col] = o;
            }
        }
    }
}

// ---------------- multi-output tf32 GEMM: A staged once, NC chunks, FP16 outputs ----------------
struct MultiOut {
    __half* ptr[5];
    int     stride[5];   // in half elements
};

template<int NC>
__global__ __launch_bounds__(256) void mma_gemm_multi(
        const float* __restrict__ A, const float* __restrict__ PW,
        const float* __restrict__ PB, MultiOut mo, int N)
{
    constexpr int KP = HDIM + 4;
    extern __shared__ uint32_t smu[];
    uint32_t* As = smu;            // 128 * KP
    uint32_t* Bs = smu + 128*KP;   // 128 * 132

    int tid = threadIdx.x;
    int row0 = blockIdx.x * 128;

    for (int i = tid; i < 128*32; i += 256) {
        int r = i >> 5, c4 = i & 31;
        int n = row0 + r;
        float4 v = make_float4(0.f, 0.f, 0.f, 0.f);
        if (n < N) v = ((const float4*)A)[(size_t)n*32 + c4];
        uint32_t* dst = &As[r*KP + c4*4];
        dst[0] = f2tf32(v.x); dst[1] = f2tf32(v.y);
        dst[2] = f2tf32(v.z); dst[3] = f2tf32(v.w);
    }

    int lane = tid & 31, w = tid >> 5;
    int wm = (w & 1) * 64;
    int wn = (w >> 1) * 32;
    int lg = lane >> 2;
    int lt = lane & 3;

    #pragma unroll
    for (int c = 0; c < NC; c++) {
        __syncthreads();
        const float4* B4 = (const float4*)(PW + (size_t)c * HDIM * HDIM);
        for (int i = tid; i < 128*32; i += 256) {
            int k = i >> 5, c4 = i & 31;
            float4 v = B4[i];
            uint32_t* dst = &Bs[k*132 + c4*4];
            dst[0] = f2tf32(v.x); dst[1] = f2tf32(v.y);
            dst[2] = f2tf32(v.z); dst[3] = f2tf32(v.w);
        }
        __syncthreads();

        float acc[4][4][4];
        #pragma unroll
        for (int mt = 0; mt < 4; mt++)
            #pragma unroll
            for (int nt = 0; nt < 4; nt++)
                #pragma unroll
                for (int j = 0; j < 4; j++) acc[mt][nt][j] = 0.f;

        #pragma unroll 2
        for (int k0 = 0; k0 < HDIM; k0 += 8) {
            uint32_t af[4][4];
            #pragma unroll
            for (int mt = 0; mt < 4; mt++) {
                int r = wm + mt*16 + lg;
                af[mt][0] = As[r*KP + k0 + lt];
                af[mt][1] = As[(r+8)*KP + k0 + lt];
                af[mt][2] = As[r*KP + k0 + lt + 4];
                af[mt][3] = As[(r+8)*KP + k0 + lt + 4];
            }
            uint32_t bf[4][2];
            #pragma unroll
            for (int nt = 0; nt < 4; nt++) {
                bf[nt][0] = Bs[(k0 + lt)*132 + wn + nt*8 + lg];
                bf[nt][1] = Bs[(k0 + lt + 4)*132 + wn + nt*8 + lg];
            }
            #pragma unroll
            for (int mt = 0; mt < 4; mt++)
                #pragma unroll
                for (int nt = 0; nt < 4; nt++)
                    mma_tf32(acc[mt][nt], af[mt], bf[nt]);
        }

        __half* out = mo.ptr[c];
        int st = mo.stride[c];
        const float* bb = PB + (size_t)c * HDIM;
        #pragma unroll
        for (int mt = 0; mt < 4; mt++) {
            #pragma unroll
            for (int nt = 0; nt < 4; nt++) {
                int col = wn + nt*8 + lt*2;
                float b0 = bb[col], b1 = bb[col+1];
                #pragma unroll
                for (int half = 0; half < 2; half++) {
                    int r = row0 + wm + mt*16 + lg + half*8;
                    if (r >= N) continue;
                    __half2 hv = __floats2half2_rn(acc[mt][nt][half*2 + 0] + b0,
                                                   acc[mt][nt][half*2 + 1] + b1);
                    *(__half2*)&out[(size_t)r*st + col] = hv;
                }
            }
        }
    }
}

// ---------------- CSR build ----------------
__global__ void csr_zero(int* __restrict__ deg0, int* __restrict__ deg1, int N) {
    int i = blockIdx.x * blockDim.x + threadIdx.x;
    if (i < N) { deg0[i] = 0; deg1[i] = 0; }
}

__global__ void csr_hist(const int* __restrict__ e0, const int* __restrict__ e1,
                         const int* __restrict__ e2, int E,
                         int* __restrict__ deg0, int* __restrict__ deg1) {
    int i = blockIdx.x * blockDim.x + threadIdx.x;
    if (i >= 3*E) return;
    int r = i / E, j = i - r*E;
    const int* e = (r == 0) ? e0 : (r == 1 ? e1 : e2);
    int dst = e[E + j];
    if (r == 1) atomicAdd(&deg0[dst], 1);
    else        atomicAdd(&deg1[dst], 1);
}

// Phase A: per-block tile totals. Block b (of 2*nb): tile of deg0 if b<nb else deg1.
__global__ void csr_reduce(const int* __restrict__ deg0, const int* __restrict__ deg1,
                           int* __restrict__ bsum, int N, int nb) {
    __shared__ int ws[8];
    int b = blockIdx.x;
    int arr = (b >= nb);
    int bb = arr ? b - nb : b;
    const int* deg = arr ? deg1 : deg0;
    int base = bb * 1024;
    int t = threadIdx.x;           // 256 threads
    int sum = 0;
    #pragma unroll
    for (int k = 0; k < 4; k++) {
        int idx = base + t + k*256;
        if (idx < N) sum += deg[idx];
    }
    #pragma unroll
    for (int s = 16; s > 0; s >>= 1) sum += __shfl_down_sync(0xffffffffu, sum, s);
    if ((t & 31) == 0) ws[t >> 5] = sum;
    __syncthreads();
    if (t == 0) {
        int tot = 0;
        #pragma unroll
        for (int i = 0; i < 8; i++) tot += ws[i];
        bsum[b] = tot;
    }
}

// Phase B: scan block sums (1 small block); writes exclusive block offsets in-place
// and the array totals to off0[N], off1[N].
__global__ void csr_scan_bsums(int* __restrict__ bsum,
                               int* __restrict__ off0, int* __restrict__ off1,
                               int N, int nb) {
    __shared__ int sh[512];
    int t = threadIdx.x;           // 256 threads
    for (int i = t; i < 2*nb; i += 256) sh[i] = bsum[i];
    __syncthreads();
    if (t == 0) {
        int run = 0;
        for (int i = 0; i < nb; i++) { int v = sh[i]; sh[i] = run; run += v; }
        off0[N] = run;
        run = 0;
        for (int i = nb; i < 2*nb; i++) { int v = sh[i]; sh[i] = run; run += v; }
        off1[N] = run;
    }
    __syncthreads();
    for (int i = t; i < 2*nb; i += 256) bsum[i] = sh[i];
}

// Phase C: per-tile exclusive scan + block offset; writes off and cur.
__global__ void csr_scatter_off(const int* __restrict__ deg0, const int* __restrict__ deg1,
                                const int* __restrict__ bsum,
                                int* __restrict__ off0, int* __restrict__ off1,
                                int* __restrict__ cur0, int* __restrict__ cur1,
                                int N, int nb) {
    __shared__ int ws[8];
    int b = blockIdx.x;
    int arr = (b >= nb);
    int bb = arr ? b - nb : b;
    const int* deg = arr ? deg1 : deg0;
    int* off = arr ? off1 : off0;
    int* cur = arr ? cur1 : cur0;
    int base = bb * 1024;
    int t = threadIdx.x;           // 256 threads, 4 consecutive elems each
    int lane = t & 31, wid = t >> 5;
    int i0 = base + t*4;

    int v[4];
    #pragma unroll
    for (int k = 0; k < 4; k++) v[k] = (i0 + k < N) ? deg[i0 + k] : 0;
    int s = v[0] + v[1] + v[2] + v[3];

    int incl = s;
    #pragma unroll
    for (int d = 1; d < 32; d <<= 1) {
        int u = __shfl_up_sync(0xffffffffu, incl, d);
        if (lane >= d) incl += u;
    }
    if (lane == 31) ws[wid] = incl;
    __syncthreads();
    if (t < 8) {
        int wv = ws[t];
        int wincl = wv;
        #pragma unroll
        for (int d = 1; d < 8; d <<= 1) {
            int u = __shfl_up_sync(0xffu, wincl, d);
            if (t >= d) wincl += u;
        }
        ws[t] = wincl - wv;
    }
    __syncthreads();

    int excl = bsum[b] + ws[wid] + incl - s;
    #pragma unroll
    for (int k = 0; k < 4; k++) {
        int idx = i0 + k;
        if (idx < N) { off[idx] = excl; cur[idx] = excl; }
        excl += v[k];
    }
}

__global__ void csr_fill(const int* __restrict__ e0, const int* __restrict__ e1,
                         const int* __restrict__ e2, int E,
                         int* __restrict__ cur0, int* __restrict__ cur1,
                         int* __restrict__ list0, int* __restrict__ list1) {
    int i = blockIdx.x * blockDim.x + threadIdx.x;
    if (i >= 3*E) return;
    int r = i / E, j = i - r*E;
    const int* e = (r == 0) ? e0 : (r == 1 ? e1 : e2);
    int src = e[j], dst = e[E + j];
    if (r == 1) {
        int p = atomicAdd(&cur0[dst], 1);
        list0[p] = src;
    } else {
        int p = atomicAdd(&cur1[dst], 1);
        list1[p] = src | ((r == 2) ? (1 << 20) : 0);
    }
}

// ---------------- gather edge pass: warp per dst node, register accumulation ----------------
// Writes Ag[n] = gelu(msg[n]/den[n]) directly (0 if no in-edges).
template<bool TWO>
__global__ void gather_kernel(const int* __restrict__ off, const int* __restrict__ list,
                              const __half* __restrict__ q,
                              const __half* __restrict__ kva, const __half* __restrict__ kvb,
                              const float* __restrict__ prelA, const float* __restrict__ prelB,
                              float* __restrict__ Ag, int N)
{
    int g = blockIdx.x * blockDim.x + threadIdx.x;
    int w = g >> 5;
    if (w >= N) return;
    int lane = threadIdx.x & 31;
    int h = lane >> 3, sub = lane & 7;
    int col = h*DHEAD + sub*4;

    const __half2* qp = (const __half2*)&q[(size_t)w*HDIM + col];
    float2 q0 = __half22float2(qp[0]), q1 = __half22float2(qp[1]);
    float pA = __ldg(&prelA[h]) * INV_SQRT_D;
    float pB = TWO ? (__ldg(&prelB[h]) * INV_SQRT_D) : 0.f;

    float den = 0.f;
    float4 macc = make_float4(0.f, 0.f, 0.f, 0.f);
    int s0 = __ldg(&off[w]), s1 = __ldg(&off[w+1]);
    for (int j = s0; j < s1; j++) {
        int entry = __ldg(&list[j]);
        int src = entry & 0xFFFFF;
        const __half* kvbase = kva;
        float p = pA;
        if (TWO && (entry >> 20)) { kvbase = kvb; p = pB; }
        const __half2* kp = (const __half2*)&kvbase[(size_t)src*256 + col];
        const __half2* vp = (const __half2*)&kvbase[(size_t)src*256 + 128 + col];
        float2 k0 = __half22float2(kp[0]), k1 = __half22float2(kp[1]);
        float2 v0 = __half22float2(vp[0]), v1 = __half22float2(vp[1]);
        float s = q0.x*k0.x + q0.y*k0.y + q1.x*k1.x + q1.y*k1.y;
        s += __shfl_xor_sync(0xffffffffu, s, 1);
        s += __shfl_xor_sync(0xffffffffu, s, 2);
        s += __shfl_xor_sync(0xffffffffu, s, 4);
        float e = expf(s * p);
        den += e;
        macc.x += e*v0.x; macc.y += e*v0.y; macc.z += e*v1.x; macc.w += e*v1.y;
    }
    float inv = (den > 0.f) ? 1.f/den : 0.f;
    float4 o;
    o.x = gelu_exact(macc.x * inv);
    o.y = gelu_exact(macc.y * inv);
    o.z = gelu_exact(macc.z * inv);
    o.w = gelu_exact(macc.w * inv);
    *(float4*)&Ag[(size_t)w*HDIM + col] = o;
}

// ---------------- host orchestration ----------------
extern "C" void kernel_launch(void* const* d_in, const int* in_sizes, int n_in,
                              void* d_out, int out_size)
{
    const float* x_region = (const float*)d_in[0];
    const float* x_site   = (const float*)d_in[1];
    const float* pWr = (const float*)d_in[2];
    const float* pbr = (const float*)d_in[3];
    const float* pWs = (const float*)d_in[4];
    const float* pbs = (const float*)d_in[5];
    const float* Wk  = (const float*)d_in[6];
    const float* bk  = (const float*)d_in[7];
    const float* Wq  = (const float*)d_in[8];
    const float* bq  = (const float*)d_in[9];
    const float* Wv  = (const float*)d_in[10];
    const float* bv  = (const float*)d_in[11];
    const float* Wo  = (const float*)d_in[12];
    const float* bo  = (const float*)d_in[13];
    const float* skip = (const float*)d_in[14];
    const float* Krel = (const float*)d_in[15];
    const float* Vrel = (const float*)d_in[16];
    const float* prel = (const float*)d_in[17];
    const int* edges[3] = { (const int*)d_in[18], (const int*)d_in[19], (const int*)d_in[20] };

    int N = in_sizes[0] / 64;
    int E = in_sizes[18] / 2;

    float* base = nullptr;
    cudaGetSymbolAddress((void**)&base, g_scratch);

    float* xs[2]    = { base + O_XS0,  base + O_XS1 };
    __half* qb[2]   = { (__half*)(base + O_Q0), (__half*)(base + O_Q1) };
    __half* ktvt[3] = { (__half*)(base + O_KTVT0), (__half*)(base + O_KTVT1), (__half*)(base + O_KTVT2) };
    float* Ag[2]    = { base + O_AG0, base + O_AG1 };
    float* PW = base + O_PW;
    float* PB = base + O_PB;
    int* ci = (int*)(base + O_CSR);
    int* deg0 = ci;            int* deg1 = ci + HN;
    int* off0 = ci + 2*HN;     int* off1 = ci + 3*HN + 1;
    int* cur0 = ci + 4*HN + 2; int* cur1 = ci + 5*HN + 2;
    int* bsum = ci + 6*HN + 2;
    int* list0 = ci + 6*HN + 2 + 512; int* list1 = list0 + EN;

    const int SM128 = (128*132 + 128*132 + 128) * 4;
    const int SM64  = (128*68  + 64*132  + 128) * 4;
    const int SM32  = (128*36  + 32*132  + 128) * 4;
    const int SMM   = (128*132 + 128*132) * 4;
    cudaFuncSetAttribute(mma_gemm<128>, cudaFuncAttributeMaxDynamicSharedMemorySize, SM128);
    cudaFuncSetAttribute(mma_gemm<64>,  cudaFuncAttributeMaxDynamicSharedMemorySize, SM64);
    cudaFuncSetAttribute(mma_gemm<32>,  cudaFuncAttributeMaxDynamicSharedMemorySize, SM32);
    cudaFuncSetAttribute(mma_gemm_multi<3>, cudaFuncAttributeMaxDynamicSharedMemorySize, SMM);
    cudaFuncSetAttribute(mma_gemm_multi<5>, cudaFuncAttributeMaxDynamicSharedMemorySize, SMM);

    int gemmGrid = (N + 127) / 128;
    int nodeGrid = (N*32 + 255) / 256;
    int eGrid3   = (3*E + 255) / 256;
    int nGrid    = (N + 255) / 256;
    int nb       = (N + 1023) / 1024;   // tiles per deg array (<=256 for N<=262144)

    // 0) packed weight chunks + CSR build (edges constant across layers)
    pack_kernel<<<16, 256>>>(Wq, bq, Wk, bk, Wv, bv, Krel, Vrel, PW, PB);
    csr_zero<<<nGrid, 256>>>(deg0, deg1, N);
    csr_hist<<<eGrid3, 256>>>(edges[0], edges[1], edges[2], E, deg0, deg1);
    csr_reduce<<<2*nb, 256>>>(deg0, deg1, bsum, N, nb);
    csr_scan_bsums<<<1, 256>>>(bsum, off0, off1, N, nb);
    csr_scatter_off<<<2*nb, 256>>>(deg0, deg1, bsum, off0, off1, cur0, cur1, N, nb);
    csr_fill<<<eGrid3, 256>>>(edges[0], edges[1], edges[2], E, cur0, cur1, list0, list1);

    // 1) input projections
    mma_gemm<64><<<gemmGrid, 256, SM64>>>(x_region, pWr, pbr, xs[0], nullptr, nullptr, N, 0);
    mma_gemm<32><<<gemmGrid, 256, SM32>>>(x_site,   pWs, pbs, xs[1], nullptr, nullptr, N, 0);

    const int L = 2;
    for (int l = 0; l < L; l++) {
        // type 0: q + ktvt for edge type 0  (chunks 0..2)
        {
            MultiOut mo;
            mo.ptr[0] = qb[0];          mo.stride[0] = 128;
            mo.ptr[1] = ktvt[0];        mo.stride[1] = 256;
            mo.ptr[2] = ktvt[0] + 128;  mo.stride[2] = 256;
            mo.ptr[3] = nullptr; mo.ptr[4] = nullptr;
            mo.stride[3] = 0; mo.stride[4] = 0;
            mma_gemm_multi<3><<<gemmGrid, 256, SMM>>>(xs[0], PW + (size_t)(l*8+0)*HDIM*HDIM,
                                                      PB + (size_t)(l*8+0)*HDIM, mo, N);
        }
        // type 1: q + ktvt for edge types 1,2  (chunks 3..7)
        {
            MultiOut mo;
            mo.ptr[0] = qb[1];          mo.stride[0] = 128;
            mo.ptr[1] = ktvt[1];        mo.stride[1] = 256;
            mo.ptr[2] = ktvt[1] + 128;  mo.stride[2] = 256;
            mo.ptr[3] = ktvt[2];        mo.stride[3] = 256;
            mo.ptr[4] = ktvt[2] + 128;  mo.stride[4] = 256;
            mma_gemm_multi<5><<<gemmGrid, 256, SMM>>>(xs[1], PW + (size_t)(l*8+3)*HDIM*HDIM,
                                                      PB + (size_t)(l*8+3)*HDIM, mo, N);
        }

        // gather edge pass (per dst type), writes pre-activated finalize input
        // type 0 dst: edge type r1 (src type 1, ktvt[1], prel[l][1])
        gather_kernel<false><<<nodeGrid, 256>>>(off0, list0, qb[0], ktvt[1], nullptr,
                                                prel + (size_t)(l*3+1)*NHEAD, nullptr,
                                                Ag[0], N);
        // type 1 dst: edge types r0 (ktvt[0], prel[l][0]) and r2 (ktvt[2], prel[l][2])
        gather_kernel<true><<<nodeGrid, 256>>>(off1, list1, qb[1], ktvt[0], ktvt[2],
                                               prel + (size_t)(l*3+0)*NHEAD,
                                               prel + (size_t)(l*3+2)*NHEAD,
                                               Ag[1], N);

        // finalize: out = relu(a*(Ag@Wo + bo) + (1-a)*xs)
        for (int t = 0; t < 2; t++) {
            float* Cptr = (l == L-1) ? ((float*)d_out + (size_t)t*N*HDIM) : xs[t];
            mma_gemm<128><<<gemmGrid, 256, SM128>>>(Ag[t], Wo + (size_t)(l*2+t)*HDIM*HDIM,
                                                    bo + (size_t)(l*2+t)*HDIM, Cptr,
                                                    xs[t], skip + l*2 + t, N, 2);
        }
    }
}

// round 15
// speedup vs baseline: 1.0939x; 1.0164x over previous
#include <cuda_runtime.h>
#include <cuda_fp16.h>
#include <math.h>
#include <stdint.h>

// Problem constants (fixed shapes for this problem)
#define HN 100000      // nodes per type
#define EN 200000      // edges per edge type
#define HDIM 128       // hidden
#define NHEAD 4
#define DHEAD 32

static const float INV_SQRT_D = 0.17677669529663687f; // 1/sqrt(32)

// ---------------- scratch layout ----------------
constexpr size_t SN = (size_t)HN * HDIM;       // one [N,128] fp32 buffer (= N*512 bytes)
constexpr size_t O_XS0   = 0;
constexpr size_t O_XS1   = SN;
constexpr size_t O_Q0    = 2*SN;               // fp16 [N,128] (half used)
constexpr size_t O_Q1    = 3*SN;
constexpr size_t O_KTVT0 = 4*SN;               // fp16 [N,256] = exactly SN floats
constexpr size_t O_KTVT1 = 5*SN;
constexpr size_t O_KTVT2 = 6*SN;
constexpr size_t O_AG0   = 7*SN;               // fp32 [N,128] pre-activated finalize input
constexpr size_t O_AG1   = 8*SN;
constexpr size_t O_PW    = 9*SN;               // 16 chunks of 128*128
constexpr size_t O_PB    = O_PW + (size_t)16*HDIM*HDIM;
constexpr size_t O_CSR   = O_PB + (size_t)16*HDIM;   // int region (1 int = 1 float slot)
// int offsets within CSR region:
//   deg0:[0,N) deg1:[N,2N) off0:[2N,3N+1) off1:[3N+1,4N+2)
//   cur0:[4N+2,5N+2) cur1:[5N+2,6N+2) bsum:[6N+2,6N+2+512)
//   list0:[6N+514, +EN) list1:[..., +2EN)
constexpr size_t CSR_INTS = (size_t)6*HN + 2 + 512 + (size_t)3*EN;
constexpr size_t SCRATCH_TOTAL = O_CSR + CSR_INTS;

__device__ float g_scratch[SCRATCH_TOTAL];

// ---------------- helpers ----------------
__device__ __forceinline__ float gelu_exact(float x) {
    return 0.5f * x * (1.0f + erff(x * 0.70710678118654752f));
}

__device__ __forceinline__ uint32_t f2tf32(float x) {
    uint32_t u;
    asm("cvt.rna.tf32.f32 %0, %1;" : "=r"(u) : "f"(x));
    return u;
}

__device__ __forceinline__ void mma_tf32(float c[4], const uint32_t a[4], const uint32_t b[2]) {
    asm volatile(
        "mma.sync.aligned.m16n8k8.row.col.f32.tf32.tf32.f32 "
        "{%0,%1,%2,%3}, {%4,%5,%6,%7}, {%8,%9}, {%0,%1,%2,%3};"
        : "+f"(c[0]), "+f"(c[1]), "+f"(c[2]), "+f"(c[3])
        : "r"(a[0]), "r"(a[1]), "r"(a[2]), "r"(a[3]), "r"(b[0]), "r"(b[1]));
}

// ---------------- pack kernel (unchanged chunk map) ----------------
__global__ void pack_kernel(const float* __restrict__ Wq, const float* __restrict__ bq,
                            const float* __restrict__ Wk, const float* __restrict__ bk,
                            const float* __restrict__ Wv, const float* __restrict__ bv,
                            const float* __restrict__ Krel, const float* __restrict__ Vrel,
                            float* __restrict__ PW, float* __restrict__ PB)
{
    int b = blockIdx.x;     // 0..15
    int l = b >> 3, c = b & 7;
    float* WO = PW + (size_t)b * HDIM * HDIM;
    float* bO = PB + (size_t)b * HDIM;

    if (c == 0 || c == 3) {
        int t = (c == 3);
        const float* W = Wq + (size_t)(l*2 + t) * HDIM * HDIM;
        const float* bb = bq + (size_t)(l*2 + t) * HDIM;
        for (int i = threadIdx.x; i < HDIM*HDIM; i += blockDim.x) WO[i] = W[i];
        if (threadIdx.x < HDIM) bO[threadIdx.x] = bb[threadIdx.x];
        return;
    }

    int kv, r, s;
    if (c == 1) { kv = 0; r = 0; s = 0; }
    else if (c == 2) { kv = 1; r = 0; s = 0; }
    else if (c == 4) { kv = 0; r = 1; s = 1; }
    else if (c == 5) { kv = 1; r = 1; s = 1; }
    else if (c == 6) { kv = 0; r = 2; s = 1; }
    else { kv = 1; r = 2; s = 1; }

    const float* W  = (kv ? Wv : Wk) + (size_t)(l*2 + s) * HDIM * HDIM;
    const float* bb = (kv ? bv : bk) + (size_t)(l*2 + s) * HDIM;
    const float* R  = (kv ? Vrel : Krel) + (size_t)(l*3 + r) * NHEAD * DHEAD * DHEAD;

    __shared__ float Rs[NHEAD*DHEAD*DHEAD];
    for (int i = threadIdx.x; i < NHEAD*DHEAD*DHEAD; i += blockDim.x) Rs[i] = R[i];
    __syncthreads();

    for (int o = threadIdx.x; o < HDIM*HDIM; o += blockDim.x) {
        int i = o >> 7, j = o & 127;
        int h = j >> 5, e = j & 31;
        float sum = 0.f;
        #pragma unroll
        for (int d = 0; d < DHEAD; d++)
            sum += W[i*HDIM + h*DHEAD + d] * Rs[(h*DHEAD + d)*DHEAD + e];
        WO[o] = sum;
    }
    if (threadIdx.x < HDIM) {
        int j = threadIdx.x, h = j >> 5, e = j & 31;
        float sum = 0.f;
        #pragma unroll
        for (int d = 0; d < DHEAD; d++)
            sum += bb[h*DHEAD + d] * Rs[(h*DHEAD + d)*DHEAD + e];
        bO[j] = sum;
    }
}

// ---------------- single-output tf32 GEMM, fp32 out (input proj + finalize) ----------------
// flags bit1: post skip-blend + relu (reads Cold)
template<int K>
__global__ __launch_bounds__(256) void mma_gemm(
        const float* __restrict__ A, const float* __restrict__ B,
        const float* __restrict__ bias, float* __restrict__ C,
        const float* __restrict__ Cold, const float* __restrict__ skipPtr,
        int N, int flags)
{
    constexpr int KP = K + 4;
    constexpr int K4 = K / 4;
    extern __shared__ uint32_t smu[];
    uint32_t* As = smu;                  // 128 * KP
    uint32_t* Bs = smu + 128*KP;         // K * 132
    float* biass = (float*)(Bs + K*132); // 128

    int tid = threadIdx.x;
    int row0 = blockIdx.x * 128;

    if (tid < 128) biass[tid] = bias[tid];

    const float4* B4 = (const float4*)B;
    for (int i = tid; i < K*32; i += 256) {
        int k = i >> 5, c4 = i & 31;
        float4 v = B4[i];
        uint32_t* dst = &Bs[k*132 + c4*4];
        dst[0] = f2tf32(v.x); dst[1] = f2tf32(v.y);
        dst[2] = f2tf32(v.z); dst[3] = f2tf32(v.w);
    }

    for (int i = tid; i < 128*K4; i += 256) {
        int r = i / K4, c4 = i % K4;
        int n = row0 + r;
        float4 v = make_float4(0.f, 0.f, 0.f, 0.f);
        if (n < N) v = ((const float4*)A)[(size_t)n*K4 + c4];
        uint32_t* dst = &As[r*KP + c4*4];
        dst[0] = f2tf32(v.x); dst[1] = f2tf32(v.y);
        dst[2] = f2tf32(v.z); dst[3] = f2tf32(v.w);
    }
    __syncthreads();

    int lane = tid & 31, w = tid >> 5;
    int wm = (w & 1) * 64;
    int wn = (w >> 1) * 32;
    int lg = lane >> 2;
    int lt = lane & 3;

    float acc[4][4][4];
    #pragma unroll
    for (int mt = 0; mt < 4; mt++)
        #pragma unroll
        for (int nt = 0; nt < 4; nt++)
            #pragma unroll
            for (int j = 0; j < 4; j++) acc[mt][nt][j] = 0.f;

    #pragma unroll 2
    for (int k0 = 0; k0 < K; k0 += 8) {
        uint32_t af[4][4];
        #pragma unroll
        for (int mt = 0; mt < 4; mt++) {
            int r = wm + mt*16 + lg;
            af[mt][0] = As[r*KP + k0 + lt];
            af[mt][1] = As[(r+8)*KP + k0 + lt];
            af[mt][2] = As[r*KP + k0 + lt + 4];
            af[mt][3] = As[(r+8)*KP + k0 + lt + 4];
        }
        uint32_t bf[4][2];
        #pragma unroll
        for (int nt = 0; nt < 4; nt++) {
            bf[nt][0] = Bs[(k0 + lt)*132 + wn + nt*8 + lg];
            bf[nt][1] = Bs[(k0 + lt + 4)*132 + wn + nt*8 + lg];
        }
        #pragma unroll
        for (int mt = 0; mt < 4; mt++)
            #pragma unroll
            for (int nt = 0; nt < 4; nt++)
                mma_tf32(acc[mt][nt], af[mt], bf[nt]);
    }

    bool blend = flags & 2;
    float askip = 0.f;
    if (blend) askip = 1.f / (1.f + expf(-skipPtr[0]));

    #pragma unroll
    for (int mt = 0; mt < 4; mt++) {
        #pragma unroll
        for (int nt = 0; nt < 4; nt++) {
            int col = wn + nt*8 + lt*2;
            float b0 = biass[col], b1 = biass[col+1];
            #pragma unroll
            for (int half = 0; half < 2; half++) {
                int r = row0 + wm + mt*16 + lg + half*8;
                if (r >= N) continue;
                float2 o;
                o.x = acc[mt][nt][half*2 + 0] + b0;
                o.y = acc[mt][nt][half*2 + 1] + b1;
                if (blend) {
                    float2 old = *(const float2*)&Cold[(size_t)r*HDIM + col];
                    o.x = fmaxf(askip*o.x + (1.f-askip)*old.x, 0.f);
                    o.y = fmaxf(askip*o.y + (1.f-askip)*old.y, 0.f);
                }
                *(float2*)&C[(size_t)r*HDIM + col] = o;
            }
        }
    }
}

// ---------------- multi-output tf32 GEMM: A staged once, NC chunks, FP16 outputs ----------------
struct MultiOut {
    __half* ptr[5];
    int     stride[5];   // in half elements
};

template<int NC>
__global__ __launch_bounds__(256) void mma_gemm_multi(
        const float* __restrict__ A, const float* __restrict__ PW,
        const float* __restrict__ PB, MultiOut mo, int N)
{
    constexpr int KP = HDIM + 4;
    extern __shared__ uint32_t smu[];
    uint32_t* As = smu;            // 128 * KP
    uint32_t* Bs = smu + 128*KP;   // 128 * 132

    int tid = threadIdx.x;
    int row0 = blockIdx.x * 128;

    for (int i = tid; i < 128*32; i += 256) {
        int r = i >> 5, c4 = i & 31;
        int n = row0 + r;
        float4 v = make_float4(0.f, 0.f, 0.f, 0.f);
        if (n < N) v = ((const float4*)A)[(size_t)n*32 + c4];
        uint32_t* dst = &As[r*KP + c4*4];
        dst[0] = f2tf32(v.x); dst[1] = f2tf32(v.y);
        dst[2] = f2tf32(v.z); dst[3] = f2tf32(v.w);
    }

    int lane = tid & 31, w = tid >> 5;
    int wm = (w & 1) * 64;
    int wn = (w >> 1) * 32;
    int lg = lane >> 2;
    int lt = lane & 3;

    #pragma unroll
    for (int c = 0; c < NC; c++) {
        __syncthreads();
        const float4* B4 = (const float4*)(PW + (size_t)c * HDIM * HDIM);
        for (int i = tid; i < 128*32; i += 256) {
            int k = i >> 5, c4 = i & 31;
            float4 v = B4[i];
            uint32_t* dst = &Bs[k*132 + c4*4];
            dst[0] = f2tf32(v.x); dst[1] = f2tf32(v.y);
            dst[2] = f2tf32(v.z); dst[3] = f2tf32(v.w);
        }
        __syncthreads();

        float acc[4][4][4];
        #pragma unroll
        for (int mt = 0; mt < 4; mt++)
            #pragma unroll
            for (int nt = 0; nt < 4; nt++)
                #pragma unroll
                for (int j = 0; j < 4; j++) acc[mt][nt][j] = 0.f;

        #pragma unroll 2
        for (int k0 = 0; k0 < HDIM; k0 += 8) {
            uint32_t af[4][4];
            #pragma unroll
            for (int mt = 0; mt < 4; mt++) {
                int r = wm + mt*16 + lg;
                af[mt][0] = As[r*KP + k0 + lt];
                af[mt][1] = As[(r+8)*KP + k0 + lt];
                af[mt][2] = As[r*KP + k0 + lt + 4];
                af[mt][3] = As[(r+8)*KP + k0 + lt + 4];
            }
            uint32_t bf[4][2];
            #pragma unroll
            for (int nt = 0; nt < 4; nt++) {
                bf[nt][0] = Bs[(k0 + lt)*132 + wn + nt*8 + lg];
                bf[nt][1] = Bs[(k0 + lt + 4)*132 + wn + nt*8 + lg];
            }
            #pragma unroll
            for (int mt = 0; mt < 4; mt++)
                #pragma unroll
                for (int nt = 0; nt < 4; nt++)
                    mma_tf32(acc[mt][nt], af[mt], bf[nt]);
        }

        __half* out = mo.ptr[c];
        int st = mo.stride[c];
        const float* bb = PB + (size_t)c * HDIM;
        #pragma unroll
        for (int mt = 0; mt < 4; mt++) {
            #pragma unroll
            for (int nt = 0; nt < 4; nt++) {
                int col = wn + nt*8 + lt*2;
                float b0 = bb[col], b1 = bb[col+1];
                #pragma unroll
                for (int half = 0; half < 2; half++) {
                    int r = row0 + wm + mt*16 + lg + half*8;
                    if (r >= N) continue;
                    __half2 hv = __floats2half2_rn(acc[mt][nt][half*2 + 0] + b0,
                                                   acc[mt][nt][half*2 + 1] + b1);
                    *(__half2*)&out[(size_t)r*st + col] = hv;
                }
            }
        }
    }
}

// ---------------- CSR build ----------------
__global__ void csr_zero(int* __restrict__ deg0, int* __restrict__ deg1, int N) {
    int i = blockIdx.x * blockDim.x + threadIdx.x;
    if (i < N) { deg0[i] = 0; deg1[i] = 0; }
}

__global__ void csr_hist(const int* __restrict__ e0, const int* __restrict__ e1,
                         const int* __restrict__ e2, int E,
                         int* __restrict__ deg0, int* __restrict__ deg1) {
    int i = blockIdx.x * blockDim.x + threadIdx.x;
    if (i >= 3*E) return;
    int r = i / E, j = i - r*E;
    const int* e = (r == 0) ? e0 : (r == 1 ? e1 : e2);
    int dst = e[E + j];
    if (r == 1) atomicAdd(&deg0[dst], 1);
    else        atomicAdd(&deg1[dst], 1);
}

// Phase A: per-block tile totals. Block b (of 2*nb): tile of deg0 if b<nb else deg1.
__global__ void csr_reduce(const int* __restrict__ deg0, const int* __restrict__ deg1,
                           int* __restrict__ bsum, int N, int nb) {
    __shared__ int ws[8];
    int b = blockIdx.x;
    int arr = (b >= nb);
    int bb = arr ? b - nb : b;
    const int* deg = arr ? deg1 : deg0;
    int base = bb * 1024;
    int t = threadIdx.x;           // 256 threads
    int sum = 0;
    #pragma unroll
    for (int k = 0; k < 4; k++) {
        int idx = base + t + k*256;
        if (idx < N) sum += deg[idx];
    }
    #pragma unroll
    for (int s = 16; s > 0; s >>= 1) sum += __shfl_down_sync(0xffffffffu, sum, s);
    if ((t & 31) == 0) ws[t >> 5] = sum;
    __syncthreads();
    if (t == 0) {
        int tot = 0;
        #pragma unroll
        for (int i = 0; i < 8; i++) tot += ws[i];
        bsum[b] = tot;
    }
}

// Phase B: scan block sums (1 small block); writes exclusive block offsets in-place
// and the array totals to off0[N], off1[N].
__global__ void csr_scan_bsums(int* __restrict__ bsum,
                               int* __restrict__ off0, int* __restrict__ off1,
                               int N, int nb) {
    __shared__ int sh[512];
    int t = threadIdx.x;           // 256 threads
    for (int i = t; i < 2*nb; i += 256) sh[i] = bsum[i];
    __syncthreads();
    if (t == 0) {
        int run = 0;
        for (int i = 0; i < nb; i++) { int v = sh[i]; sh[i] = run; run += v; }
        off0[N] = run;
        run = 0;
        for (int i = nb; i < 2*nb; i++) { int v = sh[i]; sh[i] = run; run += v; }
        off1[N] = run;
    }
    __syncthreads();
    for (int i = t; i < 2*nb; i += 256) bsum[i] = sh[i];
}

// Phase C: per-tile exclusive scan + block offset; writes off and cur.
__global__ void csr_scatter_off(const int* __restrict__ deg0, const int* __restrict__ deg1,
                                const int* __restrict__ bsum,
                                int* __restrict__ off0, int* __restrict__ off1,
                                int* __restrict__ cur0, int* __restrict__ cur1,
                                int N, int nb) {
    __shared__ int ws[8];
    int b = blockIdx.x;
    int arr = (b >= nb);
    int bb = arr ? b - nb : b;
    const int* deg = arr ? deg1 : deg0;
    int* off = arr ? off1 : off0;
    int* cur = arr ? cur1 : cur0;
    int base = bb * 1024;
    int t = threadIdx.x;           // 256 threads, 4 consecutive elems each
    int lane = t & 31, wid = t >> 5;
    int i0 = base + t*4;

    int v[4];
    #pragma unroll
    for (int k = 0; k < 4; k++) v[k] = (i0 + k < N) ? deg[i0 + k] : 0;
    int s = v[0] + v[1] + v[2] + v[3];

    int incl = s;
    #pragma unroll
    for (int d = 1; d < 32; d <<= 1) {
        int u = __shfl_up_sync(0xffffffffu, incl, d);
        if (lane >= d) incl += u;
    }
    if (lane == 31) ws[wid] = incl;
    __syncthreads();
    if (t < 8) {
        int wv = ws[t];
        int wincl = wv;
        #pragma unroll
        for (int d = 1; d < 8; d <<= 1) {
            int u = __shfl_up_sync(0xffu, wincl, d);
            if (t >= d) wincl += u;
        }
        ws[t] = wincl - wv;
    }
    __syncthreads();

    int excl = bsum[b] + ws[wid] + incl - s;
    #pragma unroll
    for (int k = 0; k < 4; k++) {
        int idx = i0 + k;
        if (idx < N) { off[idx] = excl; cur[idx] = excl; }
        excl += v[k];
    }
}

__global__ void csr_fill(const int* __restrict__ e0, const int* __restrict__ e1,
                         const int* __restrict__ e2, int E,
                         int* __restrict__ cur0, int* __restrict__ cur1,
                         int* __restrict__ list0, int* __restrict__ list1) {
    int i = blockIdx.x * blockDim.x + threadIdx.x;
    if (i >= 3*E) return;
    int r = i / E, j = i - r*E;
    const int* e = (r == 0) ? e0 : (r == 1 ? e1 : e2);
    int src = e[j], dst = e[E + j];
    if (r == 1) {
        int p = atomicAdd(&cur0[dst], 1);
        list0[p] = src;
    } else {
        int p = atomicAdd(&cur1[dst], 1);
        list1[p] = src | ((r == 2) ? (1 << 20) : 0);
    }
}

// ---------------- gather edge pass: warp per dst node, 2-edge software pipeline ----------------
// Writes Ag[n] = gelu(msg[n]/den[n]) directly (0 if no in-edges).
template<bool TWO>
__global__ void gather_kernel(const int* __restrict__ off, const int* __restrict__ list,
                              const __half* __restrict__ q,
                              const __half* __restrict__ kva, const __half* __restrict__ kvb,
                              const float* __restrict__ prelA, const float* __restrict__ prelB,
                              float* __restrict__ Ag, int N)
{
    int g = blockIdx.x * blockDim.x + threadIdx.x;
    int w = g >> 5;
    if (w >= N) return;
    int lane = threadIdx.x & 31;
    int h = lane >> 3, sub = lane & 7;
    int col = h*DHEAD + sub*4;

    const __half2* qp = (const __half2*)&q[(size_t)w*HDIM + col];
    float2 q0 = __half22float2(qp[0]), q1 = __half22float2(qp[1]);
    float pA = __ldg(&prelA[h]) * INV_SQRT_D;
    float pB = TWO ? (__ldg(&prelB[h]) * INV_SQRT_D) : 0.f;

    float den = 0.f;
    float4 macc = make_float4(0.f, 0.f, 0.f, 0.f);
    int s0 = __ldg(&off[w]), s1 = __ldg(&off[w+1]);

    int j = s0;
    // main loop: 2 edges per iteration; all 8 k/v loads issued before any reduction
    for (; j + 1 < s1; j += 2) {
        int eA = __ldg(&list[j]);
        int eB = __ldg(&list[j+1]);
        int srcA = eA & 0xFFFFF, srcB = eB & 0xFFFFF;
        const __half* baseA = kva; float pa = pA;
        const __half* baseB = kva; float pb = pA;
        if (TWO) {
            if (eA >> 20) { baseA = kvb; pa = pB; }
            if (eB >> 20) { baseB = kvb; pb = pB; }
        }
        const __half2* kpA = (const __half2*)&baseA[(size_t)srcA*256 + col];
        const __half2* vpA = (const __half2*)&baseA[(size_t)srcA*256 + 128 + col];
        const __half2* kpB = (const __half2*)&baseB[(size_t)srcB*256 + col];
        const __half2* vpB = (const __half2*)&baseB[(size_t)srcB*256 + 128 + col];
        // issue all loads up front
        __half2 ka0 = kpA[0], ka1 = kpA[1];
        __half2 va0 = vpA[0], va1 = vpA[1];
        __half2 kb0 = kpB[0], kb1 = kpB[1];
        __half2 vb0 = vpB[0], vb1 = vpB[1];

        // edge A
        {
            float2 k0 = __half22float2(ka0), k1 = __half22float2(ka1);
            float s = q0.x*k0.x + q0.y*k0.y + q1.x*k1.x + q1.y*k1.y;
            s += __shfl_xor_sync(0xffffffffu, s, 1);
            s += __shfl_xor_sync(0xffffffffu, s, 2);
            s += __shfl_xor_sync(0xffffffffu, s, 4);
            float e = __expf(s * pa);
            float2 v0 = __half22float2(va0), v1 = __half22float2(va1);
            den += e;
            macc.x += e*v0.x; macc.y += e*v0.y; macc.z += e*v1.x; macc.w += e*v1.y;
        }
        // edge B
        {
            float2 k0 = __half22float2(kb0), k1 = __half22float2(kb1);
            float s = q0.x*k0.x + q0.y*k0.y + q1.x*k1.x + q1.y*k1.y;
            s += __shfl_xor_sync(0xffffffffu, s, 1);
            s += __shfl_xor_sync(0xffffffffu, s, 2);
            s += __shfl_xor_sync(0xffffffffu, s, 4);
            float e = __expf(s * pb);
            float2 v0 = __half22float2(vb0), v1 = __half22float2(vb1);
            den += e;
            macc.x += e*v0.x; macc.y += e*v0.y; macc.z += e*v1.x; macc.w += e*v1.y;
        }
    }
    // tail edge
    if (j < s1) {
        int entry = __ldg(&list[j]);
        int src = entry & 0xFFFFF;
        const __half* kvbase = kva;
        float p = pA;
        if (TWO && (entry >> 20)) { kvbase = kvb; p = pB; }
        const __half2* kp = (const __half2*)&kvbase[(size_t)src*256 + col];
        const __half2* vp = (const __half2*)&kvbase[(size_t)src*256 + 128 + col];
        float2 k0 = __half22float2(kp[0]), k1 = __half22float2(kp[1]);
        float2 v0 = __half22float2(vp[0]), v1 = __half22float2(vp[1]);
        float s = q0.x*k0.x + q0.y*k0.y + q1.x*k1.x + q1.y*k1.y;
        s += __shfl_xor_sync(0xffffffffu, s, 1);
        s += __shfl_xor_sync(0xffffffffu, s, 2);
        s += __shfl_xor_sync(0xffffffffu, s, 4);
        float e = __expf(s * p);
        den += e;
        macc.x += e*v0.x; macc.y += e*v0.y; macc.z += e*v1.x; macc.w += e*v1.y;
    }

    float inv = (den > 0.f) ? 1.f/den : 0.f;
    float4 o;
    o.x = gelu_exact(macc.x * inv);
    o.y = gelu_exact(macc.y * inv);
    o.z = gelu_exact(macc.z * inv);
    o.w = gelu_exact(macc.w * inv);
    *(float4*)&Ag[(size_t)w*HDIM + col] = o;
}

// ---------------- host orchestration ----------------
extern "C" void kernel_launch(void* const* d_in, const int* in_sizes, int n_in,
                              void* d_out, int out_size)
{
    const float* x_region = (const float*)d_in[0];
    const float* x_site   = (const float*)d_in[1];
    const float* pWr = (const float*)d_in[2];
    const float* pbr = (const float*)d_in[3];
    const float* pWs = (const float*)d_in[4];
    const float* pbs = (const float*)d_in[5];
    const float* Wk  = (const float*)d_in[6];
    const float* bk  = (const float*)d_in[7];
    const float* Wq  = (const float*)d_in[8];
    const float* bq  = (const float*)d_in[9];
    const float* Wv  = (const float*)d_in[10];
    const float* bv  = (const float*)d_in[11];
    const float* Wo  = (const float*)d_in[12];
    const float* bo  = (const float*)d_in[13];
    const float* skip = (const float*)d_in[14];
    const float* Krel = (const float*)d_in[15];
    const float* Vrel = (const float*)d_in[16];
    const float* prel = (const float*)d_in[17];
    const int* edges[3] = { (const int*)d_in[18], (const int*)d_in[19], (const int*)d_in[20] };

    int N = in_sizes[0] / 64;
    int E = in_sizes[18] / 2;

    float* base = nullptr;
    cudaGetSymbolAddress((void**)&base, g_scratch);

    float* xs[2]    = { base + O_XS0,  base + O_XS1 };
    __half* qb[2]   = { (__half*)(base + O_Q0), (__half*)(base + O_Q1) };
    __half* ktvt[3] = { (__half*)(base + O_KTVT0), (__half*)(base + O_KTVT1), (__half*)(base + O_KTVT2) };
    float* Ag[2]    = { base + O_AG0, base + O_AG1 };
    float* PW = base + O_PW;
    float* PB = base + O_PB;
    int* ci = (int*)(base + O_CSR);
    int* deg0 = ci;            int* deg1 = ci + HN;
    int* off0 = ci + 2*HN;     int* off1 = ci + 3*HN + 1;
    int* cur0 = ci + 4*HN + 2; int* cur1 = ci + 5*HN + 2;
    int* bsum = ci + 6*HN + 2;
    int* list0 = ci + 6*HN + 2 + 512; int* list1 = list0 + EN;

    const int SM128 = (128*132 + 128*132 + 128) * 4;
    const int SM64  = (128*68  + 64*132  + 128) * 4;
    const int SM32  = (128*36  + 32*132  + 128) * 4;
    const int SMM   = (128*132 + 128*132) * 4;
    cudaFuncSetAttribute(mma_gemm<128>, cudaFuncAttributeMaxDynamicSharedMemorySize, SM128);
    cudaFuncSetAttribute(mma_gemm<64>,  cudaFuncAttributeMaxDynamicSharedMemorySize, SM64);
    cudaFuncSetAttribute(mma_gemm<32>,  cudaFuncAttributeMaxDynamicSharedMemorySize, SM32);
    cudaFuncSetAttribute(mma_gemm_multi<3>, cudaFuncAttributeMaxDynamicSharedMemorySize, SMM);
    cudaFuncSetAttribute(mma_gemm_multi<5>, cudaFuncAttributeMaxDynamicSharedMemorySize, SMM);

    int gemmGrid = (N + 127) / 128;
    int nodeGrid = (N*32 + 255) / 256;
    int eGrid3   = (3*E + 255) / 256;
    int nGrid    = (N + 255) / 256;
    int nb       = (N + 1023) / 1024;   // tiles per deg array (<=256 for N<=262144)

    // 0) packed weight chunks + CSR build (edges constant across layers)
    pack_kernel<<<16, 256>>>(Wq, bq, Wk, bk, Wv, bv, Krel, Vrel, PW, PB);
    csr_zero<<<nGrid, 256>>>(deg0, deg1, N);
    csr_hist<<<eGrid3, 256>>>(edges[0], edges[1], edges[2], E, deg0, deg1);
    csr_reduce<<<2*nb, 256>>>(deg0, deg1, bsum, N, nb);
    csr_scan_bsums<<<1, 256>>>(bsum, off0, off1, N, nb);
    csr_scatter_off<<<2*nb, 256>>>(deg0, deg1, bsum, off0, off1, cur0, cur1, N, nb);
    csr_fill<<<eGrid3, 256>>>(edges[0], edges[1], edges[2], E, cur0, cur1, list0, list1);

    // 1) input projections
    mma_gemm<64><<<gemmGrid, 256, SM64>>>(x_region, pWr, pbr, xs[0], nullptr, nullptr, N, 0);
    mma_gemm<32><<<gemmGrid, 256, SM32>>>(x_site,   pWs, pbs, xs[1], nullptr, nullptr, N, 0);

    const int L = 2;
    for (int l = 0; l < L; l++) {
        // type 0: q + ktvt for edge type 0  (chunks 0..2)
        {
            MultiOut mo;
            mo.ptr[0] = qb[0];          mo.stride[0] = 128;
            mo.ptr[1] = ktvt[0];        mo.stride[1] = 256;
            mo.ptr[2] = ktvt[0] + 128;  mo.stride[2] = 256;
            mo.ptr[3] = nullptr; mo.ptr[4] = nullptr;
            mo.stride[3] = 0; mo.stride[4] = 0;
            mma_gemm_multi<3><<<gemmGrid, 256, SMM>>>(xs[0], PW + (size_t)(l*8+0)*HDIM*HDIM,
                                                      PB + (size_t)(l*8+0)*HDIM, mo, N);
        }
        // type 1: q + ktvt for edge types 1,2  (chunks 3..7)
        {
            MultiOut mo;
            mo.ptr[0] = qb[1];          mo.stride[0] = 128;
            mo.ptr[1] = ktvt[1];        mo.stride[1] = 256;
            mo.ptr[2] = ktvt[1] + 128;  mo.stride[2] = 256;
            mo.ptr[3] = ktvt[2];        mo.stride[3] = 256;
            mo.ptr[4] = ktvt[2] + 128;  mo.stride[4] = 256;
            mma_gemm_multi<5><<<gemmGrid, 256, SMM>>>(xs[1], PW + (size_t)(l*8+3)*HDIM*HDIM,
                                                      PB + (size_t)(l*8+3)*HDIM, mo, N);
        }

        // gather edge pass (per dst type), writes pre-activated finalize input
        // type 0 dst: edge type r1 (src type 1, ktvt[1], prel[l][1])
        gather_kernel<false><<<nodeGrid, 256>>>(off0, list0, qb[0], ktvt[1], nullptr,
                                                prel + (size_t)(l*3+1)*NHEAD, nullptr,
                                                Ag[0], N);
        // type 1 dst: edge types r0 (ktvt[0], prel[l][0]) and r2 (ktvt[2], prel[l][2])
        gather_kernel<true><<<nodeGrid, 256>>>(off1, list1, qb[1], ktvt[0], ktvt[2],
                                               prel + (size_t)(l*3+0)*NHEAD,
                                               prel + (size_t)(l*3+2)*NHEAD,
                                               Ag[1], N);

        // finalize: out = relu(a*(Ag@Wo + bo) + (1-a)*xs)
        for (int t = 0; t < 2; t++) {
            float* Cptr = (l == L-1) ? ((float*)d_out + (size_t)t*N*HDIM) : xs[t];
            mma_gemm<128><<<gemmGrid, 256, SM128>>>(Ag[t], Wo + (size_t)(l*2+t)*HDIM*HDIM,
                                                    bo + (size_t)(l*2+t)*HDIM, Cptr,
                                                    xs[t], skip + l*2 + t, N, 2);
        }
    }
}